// round 8
// baseline (speedup 1.0000x reference)
#include <cuda_runtime.h>
#include <cuda_fp16.h>
#include <cstdint>

#define NN 100000
#define NE 1600000
#define IND 256
#define HID 128
#define OUTD 64
#define NB ((NN + 1023) / 1024)   // scan blocks

// scratch (allocation-free: __device__ globals)
__device__ int    g_eidx[2 * NE];           // normalized int32 edge index
__device__ int    g_degi[NN];               // in-degree (excl self)
__device__ int    g_scan[NN];               // block-local inclusive scan
__device__ int    g_bsum[NB];               // per-block totals
__device__ int    g_boff[NB + 1];           // scanned block totals
__device__ int    g_off[NN + 1];            // CSR offsets (by destination)
__device__ int    g_cur[NN];                // scatter cursors
__device__ int    g_src[NE];                // CSR source ids
__device__ float  g_dis[NN];
__device__ __half g_h1[(size_t)NN * HID];   // (x @ W1) * dis[row], fp16
__device__ float  g_a1[(size_t)NN * HID];   // relu'ed hidden (fp32)
__device__ __half g_h2[(size_t)NN * OUTD];  // (a1 @ W2) * dis[row], fp16

// ---------------------------------------------------------------------------
// fused: dtype-detect + convert to int32 + degree histogram
// ---------------------------------------------------------------------------
__global__ void k_convert_deg(const void* __restrict__ ei, int e) {
    // int64 edge_index with values < 2^31 has zero odd words; int32 random
    // node ids make that astronomically unlikely over 512 words.
    const int* p32 = (const int*)ei;
    int is64 = 1;
#pragma unroll 8
    for (int i = 0; i < 512; i++) is64 &= (p32[2 * i + 1] == 0);

    const long long* p64 = (const long long*)ei;
    int m = 2 * e;
    for (int i = blockIdx.x * blockDim.x + threadIdx.x; i < m;
         i += gridDim.x * blockDim.x) {
        int v = is64 ? (int)p64[i] : p32[i];
        v = min(max(v, 0), NN - 1);  // safety clamp
        g_eidx[i] = v;
        if (i >= e) atomicAdd(&g_degi[v], 1);  // col half -> in-degree
    }
}

__global__ void k_dis(int n) {
    int i = blockIdx.x * blockDim.x + threadIdx.x;
    if (i < n) g_dis[i] = rsqrtf((float)(g_degi[i] + 1));  // +1 self-loop
}

// ---------------------------------------------------------------------------
// prefix scan -> CSR offsets, then position scatter
// ---------------------------------------------------------------------------
__global__ __launch_bounds__(1024) void k_scan1(int n) {
    __shared__ int sh[1024];
    int i = blockIdx.x * 1024 + threadIdx.x;
    int v = (i < n) ? g_degi[i] : 0;
    sh[threadIdx.x] = v;
    __syncthreads();
#pragma unroll
    for (int d = 1; d < 1024; d <<= 1) {
        int t = (threadIdx.x >= d) ? sh[threadIdx.x - d] : 0;
        __syncthreads();
        sh[threadIdx.x] += t;
        __syncthreads();
    }
    if (i < n) g_scan[i] = sh[threadIdx.x];
    if (threadIdx.x == 1023) g_bsum[blockIdx.x] = sh[1023];
}

__global__ void k_scan2() {
    if (threadIdx.x == 0 && blockIdx.x == 0) {
        int acc = 0;
        g_boff[0] = 0;
        for (int b = 0; b < NB; b++) {
            acc += g_bsum[b];
            g_boff[b + 1] = acc;
        }
    }
}

__global__ void k_scan3(int n) {
    int i = blockIdx.x * blockDim.x + threadIdx.x;
    if (i >= n) return;
    int incl = g_scan[i] + g_boff[i >> 10];
    int start = incl - g_degi[i];
    g_off[i] = start;
    g_cur[i] = start;
    if (i == n - 1) g_off[n] = incl;
}

__global__ void k_scatter(int e) {
    for (int i = blockIdx.x * blockDim.x + threadIdx.x; i < e;
         i += gridDim.x * blockDim.x) {
        int c = g_eidx[e + i];
        int r = g_eidx[i];
        int pos = atomicAdd(&g_cur[c], 1);
        g_src[pos] = r;
    }
}

// ---------------------------------------------------------------------------
// 3xTF32 tensor-core GEMM: C[M,N] = (A[M,K] @ B[K,N]) * scale[row]
// OutT = float (float2 stores) or __half (half2 stores)
// ---------------------------------------------------------------------------
__device__ __forceinline__ void f32_split(float v, uint32_t& hi, uint32_t& lo) {
    asm("cvt.rna.tf32.f32 %0, %1;" : "=r"(hi) : "f"(v));
    float rem = v - __uint_as_float(hi);
    asm("cvt.rna.tf32.f32 %0, %1;" : "=r"(lo) : "f"(rem));
}

__device__ __forceinline__ void mma_tf32(float* c, const uint32_t* a,
                                         const uint32_t* b) {
    asm volatile(
        "mma.sync.aligned.m16n8k8.row.col.f32.tf32.tf32.f32 "
        "{%0,%1,%2,%3}, {%4,%5,%6,%7}, {%8,%9}, {%0,%1,%2,%3};"
        : "+f"(c[0]), "+f"(c[1]), "+f"(c[2]), "+f"(c[3])
        : "r"(a[0]), "r"(a[1]), "r"(a[2]), "r"(a[3]), "r"(b[0]), "r"(b[1]));
}

template <int K, int N, int BM, int BK, int WM, int WN, typename OutT>
__global__ __launch_bounds__((BM / WM) * (N / WN) * 32) void tf32_gemm(
    const float* __restrict__ A, const float* __restrict__ B,
    OutT* __restrict__ C, const float* __restrict__ scale, int M) {
    constexpr int BN = N;
    constexpr int WARPS_N = BN / WN;
    constexpr int NWARPS = (BM / WM) * WARPS_N;
    constexpr int THREADS = NWARPS * 32;
    constexpr int MT = WM / 16;
    constexpr int NT = WN / 8;
    constexpr int A_LOADS = (BM * BK / 4) / THREADS;
    constexpr int B_LOADS = (BK * BN / 4) / THREADS;
    constexpr int PAD = 8;

    __shared__ float As[BK][BM + PAD];
    __shared__ float Bs[BK][BN + PAD];

    const int tid = threadIdx.x;
    const int wid = tid >> 5;
    const int lane = tid & 31;
    const int p = lane >> 2;   // 0..7
    const int q = lane & 3;    // 0..3
    const int wm0 = (wid / WARPS_N) * WM;
    const int wn0 = (wid % WARPS_N) * WN;
    const int m0 = blockIdx.x * BM;

    float acc[MT][NT][4] = {};

    float4 aReg[A_LOADS], bReg[B_LOADS];
#pragma unroll
    for (int l = 0; l < A_LOADS; l++) {
        int idx = tid + l * THREADS;
        int r = idx / (BK / 4);
        int kc = (idx % (BK / 4)) * 4;
        int row = m0 + r;
        if (row >= M) row = M - 1;
        aReg[l] = *(const float4*)(A + (size_t)row * K + kc);
    }
#pragma unroll
    for (int l = 0; l < B_LOADS; l++) {
        int flat = (tid + l * THREADS) * 4;
        bReg[l] = *(const float4*)(B + flat);
    }

    for (int k0 = 0; k0 < K; k0 += BK) {
#pragma unroll
        for (int l = 0; l < A_LOADS; l++) {
            int idx = tid + l * THREADS;
            int r = idx / (BK / 4);
            int kc = (idx % (BK / 4)) * 4;
            As[kc + 0][r] = aReg[l].x;
            As[kc + 1][r] = aReg[l].y;
            As[kc + 2][r] = aReg[l].z;
            As[kc + 3][r] = aReg[l].w;
        }
#pragma unroll
        for (int l = 0; l < B_LOADS; l++) {
            int flat = (tid + l * THREADS) * 4;
            int k = flat / BN;
            int n = flat % BN;
            *(float4*)(&Bs[k][n]) = bReg[l];
        }
        __syncthreads();

        if (k0 + BK < K) {
#pragma unroll
            for (int l = 0; l < A_LOADS; l++) {
                int idx = tid + l * THREADS;
                int r = idx / (BK / 4);
                int kc = (idx % (BK / 4)) * 4;
                int row = m0 + r;
                if (row >= M) row = M - 1;
                aReg[l] = *(const float4*)(A + (size_t)row * K + k0 + BK + kc);
            }
#pragma unroll
            for (int l = 0; l < B_LOADS; l++) {
                int flat = (tid + l * THREADS) * 4;
                bReg[l] = *(const float4*)(B + (size_t)(k0 + BK) * N + flat);
            }
        }

#pragma unroll
        for (int kk = 0; kk < BK; kk += 8) {
            uint32_t ahi[MT][4], alo[MT][4];
#pragma unroll
            for (int mt = 0; mt < MT; mt++) {
                int r0 = wm0 + mt * 16 + p;
                f32_split(As[kk + q][r0],         ahi[mt][0], alo[mt][0]);
                f32_split(As[kk + q][r0 + 8],     ahi[mt][1], alo[mt][1]);
                f32_split(As[kk + q + 4][r0],     ahi[mt][2], alo[mt][2]);
                f32_split(As[kk + q + 4][r0 + 8], ahi[mt][3], alo[mt][3]);
            }
            uint32_t bhi[NT][2], blo[NT][2];
#pragma unroll
            for (int nt = 0; nt < NT; nt++) {
                int c0 = wn0 + nt * 8 + p;
                f32_split(Bs[kk + q][c0],     bhi[nt][0], blo[nt][0]);
                f32_split(Bs[kk + q + 4][c0], bhi[nt][1], blo[nt][1]);
            }
#pragma unroll
            for (int mt = 0; mt < MT; mt++)
#pragma unroll
                for (int nt = 0; nt < NT; nt++) {
                    mma_tf32(acc[mt][nt], ahi[mt], bhi[nt]);
                    mma_tf32(acc[mt][nt], ahi[mt], blo[nt]);
                    mma_tf32(acc[mt][nt], alo[mt], bhi[nt]);
                }
        }
        __syncthreads();
    }

#pragma unroll
    for (int mt = 0; mt < MT; mt++) {
        int row0 = m0 + wm0 + mt * 16 + p;
        int row1 = row0 + 8;
        float s0 = (row0 < M) ? scale[row0] : 0.0f;
        float s1 = (row1 < M) ? scale[row1] : 0.0f;
#pragma unroll
        for (int nt = 0; nt < NT; nt++) {
            int col = wn0 + nt * 8 + 2 * q;
            if (row0 < M) {
                if constexpr (sizeof(OutT) == 4) {
                    float2 v = make_float2(acc[mt][nt][0] * s0,
                                           acc[mt][nt][1] * s0);
                    *(float2*)((float*)C + (size_t)row0 * N + col) = v;
                } else {
                    __half2 v = __floats2half2_rn(acc[mt][nt][0] * s0,
                                                  acc[mt][nt][1] * s0);
                    *(__half2*)((__half*)C + (size_t)row0 * N + col) = v;
                }
            }
            if (row1 < M) {
                if constexpr (sizeof(OutT) == 4) {
                    float2 v = make_float2(acc[mt][nt][2] * s1,
                                           acc[mt][nt][3] * s1);
                    *(float2*)((float*)C + (size_t)row1 * N + col) = v;
                } else {
                    __half2 v = __floats2half2_rn(acc[mt][nt][2] * s1,
                                                  acc[mt][nt][3] * s1);
                    *(__half2*)((__half*)C + (size_t)row1 * N + col) = v;
                }
            }
        }
    }
}

// ---------------------------------------------------------------------------
// CSR pull aggregation (fp16 gathers, fp32 accumulate)
// layer1: a1[node] = relu(dis[node] * (h1[node] + sum h1[src]) + b1)
// ---------------------------------------------------------------------------
__device__ __forceinline__ void acc_h4(float4& acc, const __half2* p) {
    float2 lo = __half22float2(p[0]);
    float2 hi = __half22float2(p[1]);
    acc.x += lo.x; acc.y += lo.y; acc.z += hi.x; acc.w += hi.y;
}

__global__ __launch_bounds__(256) void k_agg1(const float* __restrict__ b1,
                                              int n) {
    int node = (blockIdx.x * blockDim.x + threadIdx.x) >> 5;
    int lane = threadIdx.x & 31;
    if (node >= n) return;
    int beg = g_off[node];
    int end = g_off[node + 1];

    float4 acc = {0.f, 0.f, 0.f, 0.f};
    acc_h4(acc, (const __half2*)(g_h1 + (size_t)node * HID) + 2 * lane);  // self

    int j = beg;
    for (; j + 32 <= end; j += 32) {
        int s = g_src[j + lane];
#pragma unroll 8
        for (int k = 0; k < 32; k++) {
            int sk = __shfl_sync(0xffffffff, s, k);
            acc_h4(acc, (const __half2*)(g_h1 + (size_t)sk * HID) + 2 * lane);
        }
    }
    if (j < end) {
        int myi = j + lane;
        int s = (myi < end) ? g_src[myi] : 0;
        int cnt = end - j;
        for (int k = 0; k < cnt; k++) {
            int sk = __shfl_sync(0xffffffff, s, k);
            acc_h4(acc, (const __half2*)(g_h1 + (size_t)sk * HID) + 2 * lane);
        }
    }

    float sc = g_dis[node];
    float4 b = ((const float4*)b1)[lane];
    float4 o;
    o.x = fmaxf(fmaf(acc.x, sc, b.x), 0.0f);
    o.y = fmaxf(fmaf(acc.y, sc, b.y), 0.0f);
    o.z = fmaxf(fmaf(acc.z, sc, b.z), 0.0f);
    o.w = fmaxf(fmaf(acc.w, sc, b.w), 0.0f);
    ((float4*)(g_a1 + (size_t)node * HID))[lane] = o;
}

// layer2: out[node] = dis[node] * (h2[node] + sum h2[src]) + b2
__global__ __launch_bounds__(256) void k_agg2(const float* __restrict__ b2,
                                              float* __restrict__ out, int n) {
    int node = (blockIdx.x * blockDim.x + threadIdx.x) >> 5;
    int lane = threadIdx.x & 31;
    if (node >= n) return;
    int beg = g_off[node];
    int end = g_off[node + 1];

    float2 acc = __half22float2(
        ((const __half2*)(g_h2 + (size_t)node * OUTD))[lane]);  // self

    int j = beg;
    for (; j + 32 <= end; j += 32) {
        int s = g_src[j + lane];
#pragma unroll 8
        for (int k = 0; k < 32; k++) {
            int sk = __shfl_sync(0xffffffff, s, k);
            float2 v = __half22float2(
                ((const __half2*)(g_h2 + (size_t)sk * OUTD))[lane]);
            acc.x += v.x; acc.y += v.y;
        }
    }
    if (j < end) {
        int myi = j + lane;
        int s = (myi < end) ? g_src[myi] : 0;
        int cnt = end - j;
        for (int k = 0; k < cnt; k++) {
            int sk = __shfl_sync(0xffffffff, s, k);
            float2 v = __half22float2(
                ((const __half2*)(g_h2 + (size_t)sk * OUTD))[lane]);
            acc.x += v.x; acc.y += v.y;
        }
    }

    float sc = g_dis[node];
    float2 b = ((const float2*)b2)[lane];
    float2 o;
    o.x = fmaf(acc.x, sc, b.x);
    o.y = fmaf(acc.y, sc, b.y);
    ((float2*)(out + (size_t)node * OUTD))[lane] = o;
}

// ---------------------------------------------------------------------------
// launch
// ---------------------------------------------------------------------------
extern "C" void kernel_launch(void* const* d_in, const int* in_sizes, int n_in,
                              void* d_out, int out_size) {
    const float* x = nullptr;
    const void* ei = nullptr;
    const float* W1 = nullptr;
    const float* b1 = nullptr;
    const float* W2 = nullptr;
    const float* b2 = nullptr;
    for (int i = 0; i < n_in; i++) {
        switch (in_sizes[i]) {
            case NN * IND:   x  = (const float*)d_in[i]; break;
            case 2 * NE:     ei = d_in[i];               break;
            case IND * HID:  W1 = (const float*)d_in[i]; break;
            case HID:        b1 = (const float*)d_in[i]; break;
            case HID * OUTD: W2 = (const float*)d_in[i]; break;
            case OUTD:       b2 = (const float*)d_in[i]; break;
            default: break;
        }
    }
    float* out = (float*)d_out;
    const int n = NN;
    const int e = NE;

    __half* h1; cudaGetSymbolAddress((void**)&h1, g_h1);
    float*  a1; cudaGetSymbolAddress((void**)&a1, g_a1);
    __half* h2; cudaGetSymbolAddress((void**)&h2, g_h2);
    float* dis; cudaGetSymbolAddress((void**)&dis, g_dis);
    int*  degi; cudaGetSymbolAddress((void**)&degi, g_degi);

    // edge normalization + CSR build
    cudaMemsetAsync(degi, 0, NN * sizeof(int));
    k_convert_deg<<<2048, 256>>>(ei, e);
    k_dis<<<(n + 255) / 256, 256>>>(n);
    k_scan1<<<NB, 1024>>>(n);
    k_scan2<<<1, 32>>>();
    k_scan3<<<(n + 255) / 256, 256>>>(n);
    k_scatter<<<1024, 256>>>(e);

    // layer 1
    tf32_gemm<IND, HID, 128, 32, 64, 32, __half>
        <<<(n + 127) / 128, 256>>>(x, W1, h1, dis, n);
    {
        long long thr = (long long)n * 32;
        k_agg1<<<(int)((thr + 255) / 256), 256>>>(b1, n);
    }

    // layer 2
    tf32_gemm<HID, OUTD, 128, 32, 32, 32, __half>
        <<<(n + 127) / 128, 256>>>(a1, W2, h2, dis, n);
    {
        long long thr = (long long)n * 32;
        k_agg2<<<(int)((thr + 255) / 256), 256>>>(b2, out, n);
    }
}

// round 11
// speedup vs baseline: 1.1128x; 1.1128x over previous
#include <cuda_runtime.h>
#include <cstdint>

#define NN 100000
#define NE 1600000
#define IND 256
#define HID 128
#define OUTD 64
#define NB ((NN + 1023) / 1024)   // scan blocks

// scratch (allocation-free: __device__ globals)
__device__ int   g_is64;
__device__ int   g_eidx[2 * NE];           // normalized int32 edge index
__device__ int   g_degi[NN];               // in-degree (excl self)
__device__ int   g_scan[NN];               // block-local inclusive scan
__device__ int   g_bsum[NB];               // per-block totals
__device__ int   g_boff[NB + 1];           // scanned block totals
__device__ int   g_off[NN + 1];            // CSR offsets (by destination)
__device__ int   g_cur[NN];                // scatter cursors
__device__ int   g_src[NE];                // CSR source ids
__device__ float g_dis[NN];
__device__ float g_h1[(size_t)NN * HID];   // x @ W1 (unscaled)
__device__ float g_a1[(size_t)NN * HID];   // relu'ed hidden
__device__ float g_h2[(size_t)NN * OUTD];  // (a1 @ W2) * dis[row]

// ---------------------------------------------------------------------------
// edge-index dtype detection + normalization + degree histogram
// ---------------------------------------------------------------------------
__global__ void k_detect(const int* __restrict__ ei32) {
    if (threadIdx.x == 0 && blockIdx.x == 0) {
        int is64 = 1;
        for (int i = 0; i < 512; i++) {
            if (ei32[2 * i + 1] != 0) { is64 = 0; break; }
        }
        g_is64 = is64;
    }
}

__global__ void k_convert_deg(const void* __restrict__ ei, int e) {
    const int is64 = g_is64;
    const long long* p64 = (const long long*)ei;
    const int* p32 = (const int*)ei;
    int m = 2 * e;
    for (int i = blockIdx.x * blockDim.x + threadIdx.x; i < m;
         i += gridDim.x * blockDim.x) {
        int v = is64 ? (int)p64[i] : p32[i];
        v = min(max(v, 0), NN - 1);  // safety clamp
        g_eidx[i] = v;
        if (i >= e) atomicAdd(&g_degi[v], 1);  // col half -> in-degree
    }
}

__global__ void k_dis(int n) {
    int i = blockIdx.x * blockDim.x + threadIdx.x;
    if (i < n) g_dis[i] = rsqrtf((float)(g_degi[i] + 1));  // +1 self-loop
}

// ---------------------------------------------------------------------------
// prefix scan -> CSR offsets, then position scatter
// ---------------------------------------------------------------------------
__global__ __launch_bounds__(1024) void k_scan1(int n) {
    __shared__ int sh[1024];
    int i = blockIdx.x * 1024 + threadIdx.x;
    int v = (i < n) ? g_degi[i] : 0;
    sh[threadIdx.x] = v;
    __syncthreads();
#pragma unroll
    for (int d = 1; d < 1024; d <<= 1) {
        int t = (threadIdx.x >= d) ? sh[threadIdx.x - d] : 0;
        __syncthreads();
        sh[threadIdx.x] += t;
        __syncthreads();
    }
    if (i < n) g_scan[i] = sh[threadIdx.x];
    if (threadIdx.x == 1023) g_bsum[blockIdx.x] = sh[1023];
}

__global__ void k_scan2() {  // single-warp shfl scan over NB block sums
    int lane = threadIdx.x;
    int carry = 0;
    if (lane == 0) g_boff[0] = 0;
    for (int base = 0; base < NB; base += 32) {
        int idx = base + lane;
        int v = (idx < NB) ? g_bsum[idx] : 0;
#pragma unroll
        for (int d = 1; d < 32; d <<= 1) {
            int t = __shfl_up_sync(0xffffffff, v, d);
            if (lane >= d) v += t;
        }
        if (idx < NB) g_boff[idx + 1] = carry + v;
        carry += __shfl_sync(0xffffffff, v, 31);
    }
}

__global__ void k_scan3(int n) {
    int i = blockIdx.x * blockDim.x + threadIdx.x;
    if (i >= n) return;
    int incl = g_scan[i] + g_boff[i >> 10];
    int start = incl - g_degi[i];
    g_off[i] = start;
    g_cur[i] = start;
    if (i == n - 1) g_off[n] = incl;
}

__global__ void k_scatter(int e) {
    for (int i = blockIdx.x * blockDim.x + threadIdx.x; i < e;
         i += gridDim.x * blockDim.x) {
        int c = g_eidx[e + i];
        int r = g_eidx[i];
        int pos = atomicAdd(&g_cur[c], 1);
        g_src[pos] = r;
    }
}

// ---------------------------------------------------------------------------
// 3xTF32 tensor-core GEMM: C[M,N] = (A[M,K] @ B[K,N]) * (scale?scale[row]:1)
// ---------------------------------------------------------------------------
__device__ __forceinline__ void f32_split(float v, uint32_t& hi, uint32_t& lo) {
    asm("cvt.rna.tf32.f32 %0, %1;" : "=r"(hi) : "f"(v));
    float rem = v - __uint_as_float(hi);
    asm("cvt.rna.tf32.f32 %0, %1;" : "=r"(lo) : "f"(rem));
}

__device__ __forceinline__ void mma_tf32(float* c, const uint32_t* a,
                                         const uint32_t* b) {
    asm volatile(
        "mma.sync.aligned.m16n8k8.row.col.f32.tf32.tf32.f32 "
        "{%0,%1,%2,%3}, {%4,%5,%6,%7}, {%8,%9}, {%0,%1,%2,%3};"
        : "+f"(c[0]), "+f"(c[1]), "+f"(c[2]), "+f"(c[3])
        : "r"(a[0]), "r"(a[1]), "r"(a[2]), "r"(a[3]), "r"(b[0]), "r"(b[1]));
}

template <int K, int N, int BM, int BK, int WM, int WN>
__global__ __launch_bounds__((BM / WM) * (N / WN) * 32) void tf32_gemm(
    const float* __restrict__ A, const float* __restrict__ B,
    float* __restrict__ C, const float* __restrict__ scale, int M) {
    constexpr int BN = N;
    constexpr int WARPS_N = BN / WN;
    constexpr int NWARPS = (BM / WM) * WARPS_N;
    constexpr int THREADS = NWARPS * 32;
    constexpr int MT = WM / 16;
    constexpr int NT = WN / 8;
    constexpr int A_LOADS = (BM * BK / 4) / THREADS;
    constexpr int B_LOADS = (BK * BN / 4) / THREADS;
    constexpr int PAD = 8;

    __shared__ float As[BK][BM + PAD];
    __shared__ float Bs[BK][BN + PAD];

    const int tid = threadIdx.x;
    const int wid = tid >> 5;
    const int lane = tid & 31;
    const int p = lane >> 2;   // 0..7
    const int q = lane & 3;    // 0..3
    const int wm0 = (wid / WARPS_N) * WM;
    const int wn0 = (wid % WARPS_N) * WN;
    const int m0 = blockIdx.x * BM;

    float acc[MT][NT][4] = {};

    float4 aReg[A_LOADS], bReg[B_LOADS];
#pragma unroll
    for (int l = 0; l < A_LOADS; l++) {
        int idx = tid + l * THREADS;
        int r = idx / (BK / 4);
        int kc = (idx % (BK / 4)) * 4;
        int row = m0 + r;
        if (row >= M) row = M - 1;
        aReg[l] = *(const float4*)(A + (size_t)row * K + kc);
    }
#pragma unroll
    for (int l = 0; l < B_LOADS; l++) {
        int flat = (tid + l * THREADS) * 4;
        bReg[l] = *(const float4*)(B + flat);
    }

    for (int k0 = 0; k0 < K; k0 += BK) {
#pragma unroll
        for (int l = 0; l < A_LOADS; l++) {
            int idx = tid + l * THREADS;
            int r = idx / (BK / 4);
            int kc = (idx % (BK / 4)) * 4;
            As[kc + 0][r] = aReg[l].x;
            As[kc + 1][r] = aReg[l].y;
            As[kc + 2][r] = aReg[l].z;
            As[kc + 3][r] = aReg[l].w;
        }
#pragma unroll
        for (int l = 0; l < B_LOADS; l++) {
            int flat = (tid + l * THREADS) * 4;
            int k = flat / BN;
            int n = flat % BN;
            *(float4*)(&Bs[k][n]) = bReg[l];
        }
        __syncthreads();

        if (k0 + BK < K) {
#pragma unroll
            for (int l = 0; l < A_LOADS; l++) {
                int idx = tid + l * THREADS;
                int r = idx / (BK / 4);
                int kc = (idx % (BK / 4)) * 4;
                int row = m0 + r;
                if (row >= M) row = M - 1;
                aReg[l] = *(const float4*)(A + (size_t)row * K + k0 + BK + kc);
            }
#pragma unroll
            for (int l = 0; l < B_LOADS; l++) {
                int flat = (tid + l * THREADS) * 4;
                bReg[l] = *(const float4*)(B + (size_t)(k0 + BK) * N + flat);
            }
        }

#pragma unroll
        for (int kk = 0; kk < BK; kk += 8) {
            uint32_t ahi[MT][4], alo[MT][4];
#pragma unroll
            for (int mt = 0; mt < MT; mt++) {
                int r0 = wm0 + mt * 16 + p;
                f32_split(As[kk + q][r0],         ahi[mt][0], alo[mt][0]);
                f32_split(As[kk + q][r0 + 8],     ahi[mt][1], alo[mt][1]);
                f32_split(As[kk + q + 4][r0],     ahi[mt][2], alo[mt][2]);
                f32_split(As[kk + q + 4][r0 + 8], ahi[mt][3], alo[mt][3]);
            }
            uint32_t bhi[NT][2], blo[NT][2];
#pragma unroll
            for (int nt = 0; nt < NT; nt++) {
                int c0 = wn0 + nt * 8 + p;
                f32_split(Bs[kk + q][c0],     bhi[nt][0], blo[nt][0]);
                f32_split(Bs[kk + q + 4][c0], bhi[nt][1], blo[nt][1]);
            }
#pragma unroll
            for (int mt = 0; mt < MT; mt++)
#pragma unroll
                for (int nt = 0; nt < NT; nt++) {
                    mma_tf32(acc[mt][nt], ahi[mt], bhi[nt]);
                    mma_tf32(acc[mt][nt], ahi[mt], blo[nt]);
                    mma_tf32(acc[mt][nt], alo[mt], bhi[nt]);
                }
        }
        __syncthreads();
    }

#pragma unroll
    for (int mt = 0; mt < MT; mt++) {
        int row0 = m0 + wm0 + mt * 16 + p;
        int row1 = row0 + 8;
        float s0 = scale ? ((row0 < M) ? scale[row0] : 0.0f) : 1.0f;
        float s1 = scale ? ((row1 < M) ? scale[row1] : 0.0f) : 1.0f;
#pragma unroll
        for (int nt = 0; nt < NT; nt++) {
            int col = wn0 + nt * 8 + 2 * q;
            if (row0 < M) {
                float2 v = make_float2(acc[mt][nt][0] * s0, acc[mt][nt][1] * s0);
                *(float2*)(C + (size_t)row0 * N + col) = v;
            }
            if (row1 < M) {
                float2 v = make_float2(acc[mt][nt][2] * s1, acc[mt][nt][3] * s1);
                *(float2*)(C + (size_t)row1 * N + col) = v;
            }
        }
    }
}

// ---------------------------------------------------------------------------
// CSR pull aggregation (fp32 gathers, dis applied per-source here)
// layer1: a1[node] = relu(dis[node] * (dis[node]*h1[node] + sum dis[s]*h1[s]) + b1)
// ---------------------------------------------------------------------------
__global__ __launch_bounds__(256) void k_agg1(const float* __restrict__ b1,
                                              int n) {
    int node = (blockIdx.x * blockDim.x + threadIdx.x) >> 5;
    int lane = threadIdx.x & 31;
    if (node >= n) return;
    int beg = g_off[node];
    int end = g_off[node + 1];
    float dn = g_dis[node];

    float4 h = ((const float4*)(g_h1 + (size_t)node * HID))[lane];  // self
    float4 acc = make_float4(dn * h.x, dn * h.y, dn * h.z, dn * h.w);

    int j = beg;
    for (; j + 32 <= end; j += 32) {
        int s = g_src[j + lane];
        float ds = g_dis[s];
#pragma unroll 8
        for (int k = 0; k < 32; k++) {
            int sk = __shfl_sync(0xffffffff, s, k);
            float dsk = __shfl_sync(0xffffffff, ds, k);
            float4 v = ((const float4*)(g_h1 + (size_t)sk * HID))[lane];
            acc.x = fmaf(dsk, v.x, acc.x);
            acc.y = fmaf(dsk, v.y, acc.y);
            acc.z = fmaf(dsk, v.z, acc.z);
            acc.w = fmaf(dsk, v.w, acc.w);
        }
    }
    if (j < end) {
        int myi = j + lane;
        int s = (myi < end) ? g_src[myi] : 0;
        float ds = (myi < end) ? g_dis[s] : 0.0f;
        int cnt = end - j;
        for (int k = 0; k < cnt; k++) {
            int sk = __shfl_sync(0xffffffff, s, k);
            float dsk = __shfl_sync(0xffffffff, ds, k);
            float4 v = ((const float4*)(g_h1 + (size_t)sk * HID))[lane];
            acc.x = fmaf(dsk, v.x, acc.x);
            acc.y = fmaf(dsk, v.y, acc.y);
            acc.z = fmaf(dsk, v.z, acc.z);
            acc.w = fmaf(dsk, v.w, acc.w);
        }
    }

    float4 b = ((const float4*)b1)[lane];
    float4 o;
    o.x = fmaxf(fmaf(acc.x, dn, b.x), 0.0f);
    o.y = fmaxf(fmaf(acc.y, dn, b.y), 0.0f);
    o.z = fmaxf(fmaf(acc.z, dn, b.z), 0.0f);
    o.w = fmaxf(fmaf(acc.w, dn, b.w), 0.0f);
    ((float4*)(g_a1 + (size_t)node * HID))[lane] = o;
}

// layer2 (h2 rows pre-scaled by dis): out[node] = dis[node]*(h2[node]+sum h2[s]) + b2
__global__ __launch_bounds__(256) void k_agg2(const float* __restrict__ b2,
                                              float* __restrict__ out, int n) {
    int node = (blockIdx.x * blockDim.x + threadIdx.x) >> 5;
    int lane = threadIdx.x & 31;
    if (node >= n) return;
    int beg = g_off[node];
    int end = g_off[node + 1];

    float2 acc = ((const float2*)(g_h2 + (size_t)node * OUTD))[lane];  // self

    int j = beg;
    for (; j + 32 <= end; j += 32) {
        int s = g_src[j + lane];
#pragma unroll 8
        for (int k = 0; k < 32; k++) {
            int sk = __shfl_sync(0xffffffff, s, k);
            float2 v = ((const float2*)(g_h2 + (size_t)sk * OUTD))[lane];
            acc.x += v.x; acc.y += v.y;
        }
    }
    if (j < end) {
        int myi = j + lane;
        int s = (myi < end) ? g_src[myi] : 0;
        int cnt = end - j;
        for (int k = 0; k < cnt; k++) {
            int sk = __shfl_sync(0xffffffff, s, k);
            float2 v = ((const float2*)(g_h2 + (size_t)sk * OUTD))[lane];
            acc.x += v.x; acc.y += v.y;
        }
    }

    float sc = g_dis[node];
    float2 b = ((const float2*)b2)[lane];
    float2 o;
    o.x = fmaf(acc.x, sc, b.x);
    o.y = fmaf(acc.y, sc, b.y);
    ((float2*)(out + (size_t)node * OUTD))[lane] = o;
}

// ---------------------------------------------------------------------------
// launch (dual-stream: GEMM1 overlaps the whole CSR build)
// ---------------------------------------------------------------------------
extern "C" void kernel_launch(void* const* d_in, const int* in_sizes, int n_in,
                              void* d_out, int out_size) {
    const float* x = nullptr;
    const void* ei = nullptr;
    const float* W1 = nullptr;
    const float* b1 = nullptr;
    const float* W2 = nullptr;
    const float* b2 = nullptr;
    for (int i = 0; i < n_in; i++) {
        switch (in_sizes[i]) {
            case NN * IND:   x  = (const float*)d_in[i]; break;
            case 2 * NE:     ei = d_in[i];               break;
            case IND * HID:  W1 = (const float*)d_in[i]; break;
            case HID:        b1 = (const float*)d_in[i]; break;
            case HID * OUTD: W2 = (const float*)d_in[i]; break;
            case OUTD:       b2 = (const float*)d_in[i]; break;
            default: break;
        }
    }
    float* out = (float*)d_out;
    const int n = NN;
    const int e = NE;

    float* h1;  cudaGetSymbolAddress((void**)&h1, g_h1);
    float* a1;  cudaGetSymbolAddress((void**)&a1, g_a1);
    float* h2;  cudaGetSymbolAddress((void**)&h2, g_h2);
    float* dis; cudaGetSymbolAddress((void**)&dis, g_dis);
    int*  degi; cudaGetSymbolAddress((void**)&degi, g_degi);

    // kernel_launch is called only for correctness + capture; a leaked
    // stream/event pair per call is bounded and keeps capture-fork simple.
    cudaStream_t sB;
    cudaEvent_t e0, e1;
    cudaStreamCreateWithFlags(&sB, cudaStreamNonBlocking);
    cudaEventCreateWithFlags(&e0, cudaEventDisableTiming);
    cudaEventCreateWithFlags(&e1, cudaEventDisableTiming);

    // fork: GEMM1 on sB (depends only on inputs)
    cudaEventRecord(e0, 0);
    cudaStreamWaitEvent(sB, e0, 0);
    tf32_gemm<IND, HID, 128, 32, 64, 32>
        <<<(n + 127) / 128, 256, 0, sB>>>(x, W1, h1, nullptr, n);
    cudaEventRecord(e1, sB);

    // default stream: CSR build
    cudaMemsetAsync(degi, 0, NN * sizeof(int));
    k_detect<<<1, 32>>>((const int*)ei);
    k_convert_deg<<<2048, 256>>>(ei, e);
    k_dis<<<(n + 255) / 256, 256>>>(n);
    k_scan1<<<NB, 1024>>>(n);
    k_scan2<<<1, 32>>>();
    k_scan3<<<(n + 255) / 256, 256>>>(n);
    k_scatter<<<1024, 256>>>(e);

    // join, then aggregation + layer 2
    cudaStreamWaitEvent(0, e1, 0);
    {
        long long thr = (long long)n * 32;
        k_agg1<<<(int)((thr + 255) / 256), 256>>>(b1, n);
    }
    tf32_gemm<HID, OUTD, 128, 32, 32, 32>
        <<<(n + 127) / 128, 256>>>(a1, W2, h2, dis, n);
    {
        long long thr = (long long)n * 32;
        k_agg2<<<(int)((thr + 255) / 256), 256>>>(b2, out, n);
    }
}

// round 12
// speedup vs baseline: 1.2146x; 1.0915x over previous
#include <cuda_runtime.h>
#include <cuda_fp16.h>
#include <cstdint>

#define NN 100000
#define NE 1600000
#define IND 256
#define HID 128
#define OUTD 64
#define NB ((NN + 1023) / 1024)   // scan blocks

// scratch (allocation-free: __device__ globals)
__device__ int    g_eidx[2 * NE];           // normalized int32 edge index
__device__ int    g_degi[NN];               // in-degree (excl self)
__device__ int    g_scan[NN];               // block-local inclusive scan
__device__ int    g_bsum[NB];               // per-block totals
__device__ int    g_boff[NB + 1];           // scanned block totals
__device__ int    g_off[NN + 1];            // CSR offsets (by destination)
__device__ int    g_cur[NN];                // scatter cursors
__device__ int    g_src[NE];                // CSR source ids
__device__ float  g_dis[NN];
__device__ __half g_h1[(size_t)NN * HID];   // x @ W1 (unscaled), fp16
__device__ float  g_a1[(size_t)NN * HID];   // relu'ed hidden (fp32)
__device__ __half g_h2[(size_t)NN * OUTD];  // (a1 @ W2) * dis[row], fp16

// ---------------------------------------------------------------------------
// convert + degree histogram (per-block dtype self-detect, no extra kernel)
// ---------------------------------------------------------------------------
__global__ void k_convert_deg(const void* __restrict__ ei, int e) {
    __shared__ int sh_is64;
    if (threadIdx.x < 32) {
        // warp 0: int64 values < 2^31 have zero odd 32-bit words.
        const int* p = (const int*)ei;
        int bad = 0;
#pragma unroll
        for (int k = 0; k < 16; k++)
            bad |= p[2 * (threadIdx.x * 16 + k) + 1];
        bad = __any_sync(0xffffffff, bad != 0);
        if (threadIdx.x == 0) sh_is64 = !bad;
    }
    __syncthreads();
    const int is64 = sh_is64;

    const long long* p64 = (const long long*)ei;
    const int* p32 = (const int*)ei;
    int m = 2 * e;
    for (int i = blockIdx.x * blockDim.x + threadIdx.x; i < m;
         i += gridDim.x * blockDim.x) {
        int v = is64 ? (int)p64[i] : p32[i];
        v = min(max(v, 0), NN - 1);  // safety clamp
        g_eidx[i] = v;
        if (i >= e) atomicAdd(&g_degi[v], 1);  // col half -> in-degree
    }
}

// ---------------------------------------------------------------------------
// prefix scan -> CSR offsets (+dis), then position scatter
// ---------------------------------------------------------------------------
__global__ __launch_bounds__(1024) void k_scan1(int n) {
    __shared__ int wsum[32];
    int tid = threadIdx.x;
    int lane = tid & 31;
    int wid = tid >> 5;
    int i = blockIdx.x * 1024 + tid;
    int v = (i < n) ? g_degi[i] : 0;
    int incl = v;
#pragma unroll
    for (int d = 1; d < 32; d <<= 1) {
        int t = __shfl_up_sync(0xffffffff, incl, d);
        if (lane >= d) incl += t;
    }
    if (lane == 31) wsum[wid] = incl;
    __syncthreads();
    if (wid == 0) {
        int w = wsum[lane];
#pragma unroll
        for (int d = 1; d < 32; d <<= 1) {
            int t = __shfl_up_sync(0xffffffff, w, d);
            if (lane >= d) w += t;
        }
        wsum[lane] = w;
    }
    __syncthreads();
    int wpre = (wid > 0) ? wsum[wid - 1] : 0;
    incl += wpre;
    if (i < n) g_scan[i] = incl;
    if (tid == 1023) g_bsum[blockIdx.x] = incl;
}

__global__ void k_scan2() {  // single-warp shfl scan over NB block sums
    int lane = threadIdx.x;
    int carry = 0;
    if (lane == 0) g_boff[0] = 0;
    for (int base = 0; base < NB; base += 32) {
        int idx = base + lane;
        int v = (idx < NB) ? g_bsum[idx] : 0;
#pragma unroll
        for (int d = 1; d < 32; d <<= 1) {
            int t = __shfl_up_sync(0xffffffff, v, d);
            if (lane >= d) v += t;
        }
        if (idx < NB) g_boff[idx + 1] = carry + v;
        carry += __shfl_sync(0xffffffff, v, 31);
    }
}

__global__ void k_scan3(int n) {  // offsets + cursors + dis
    int i = blockIdx.x * blockDim.x + threadIdx.x;
    if (i >= n) return;
    int deg = g_degi[i];
    int incl = g_scan[i] + g_boff[i >> 10];
    int start = incl - deg;
    g_off[i] = start;
    g_cur[i] = start;
    g_dis[i] = rsqrtf((float)(deg + 1));  // +1 self-loop
    if (i == n - 1) g_off[n] = incl;
}

__global__ void k_scatter(int e) {
    for (int i = blockIdx.x * blockDim.x + threadIdx.x; i < e;
         i += gridDim.x * blockDim.x) {
        int c = g_eidx[e + i];
        int r = g_eidx[i];
        int pos = atomicAdd(&g_cur[c], 1);
        g_src[pos] = r;
    }
}

// ---------------------------------------------------------------------------
// 3xTF32 tensor-core GEMM: C[M,N] = (A[M,K] @ B[K,N]) * (scale?scale[row]:1)
// OutT = float (float2 stores) or __half (half2 stores)
// ---------------------------------------------------------------------------
__device__ __forceinline__ void f32_split(float v, uint32_t& hi, uint32_t& lo) {
    asm("cvt.rna.tf32.f32 %0, %1;" : "=r"(hi) : "f"(v));
    float rem = v - __uint_as_float(hi);
    asm("cvt.rna.tf32.f32 %0, %1;" : "=r"(lo) : "f"(rem));
}

__device__ __forceinline__ void mma_tf32(float* c, const uint32_t* a,
                                         const uint32_t* b) {
    asm volatile(
        "mma.sync.aligned.m16n8k8.row.col.f32.tf32.tf32.f32 "
        "{%0,%1,%2,%3}, {%4,%5,%6,%7}, {%8,%9}, {%0,%1,%2,%3};"
        : "+f"(c[0]), "+f"(c[1]), "+f"(c[2]), "+f"(c[3])
        : "r"(a[0]), "r"(a[1]), "r"(a[2]), "r"(a[3]), "r"(b[0]), "r"(b[1]));
}

template <int K, int N, int BM, int BK, int WM, int WN, typename OutT>
__global__ __launch_bounds__((BM / WM) * (N / WN) * 32) void tf32_gemm(
    const float* __restrict__ A, const float* __restrict__ B,
    OutT* __restrict__ C, const float* __restrict__ scale, int M) {
    constexpr int BN = N;
    constexpr int WARPS_N = BN / WN;
    constexpr int NWARPS = (BM / WM) * WARPS_N;
    constexpr int THREADS = NWARPS * 32;
    constexpr int MT = WM / 16;
    constexpr int NT = WN / 8;
    constexpr int A_LOADS = (BM * BK / 4) / THREADS;
    constexpr int B_LOADS = (BK * BN / 4) / THREADS;
    constexpr int PAD = 8;

    __shared__ float As[BK][BM + PAD];
    __shared__ float Bs[BK][BN + PAD];

    const int tid = threadIdx.x;
    const int wid = tid >> 5;
    const int lane = tid & 31;
    const int p = lane >> 2;   // 0..7
    const int q = lane & 3;    // 0..3
    const int wm0 = (wid / WARPS_N) * WM;
    const int wn0 = (wid % WARPS_N) * WN;
    const int m0 = blockIdx.x * BM;

    float acc[MT][NT][4] = {};

    float4 aReg[A_LOADS], bReg[B_LOADS];
#pragma unroll
    for (int l = 0; l < A_LOADS; l++) {
        int idx = tid + l * THREADS;
        int r = idx / (BK / 4);
        int kc = (idx % (BK / 4)) * 4;
        int row = m0 + r;
        if (row >= M) row = M - 1;
        aReg[l] = *(const float4*)(A + (size_t)row * K + kc);
    }
#pragma unroll
    for (int l = 0; l < B_LOADS; l++) {
        int flat = (tid + l * THREADS) * 4;
        bReg[l] = *(const float4*)(B + flat);
    }

    for (int k0 = 0; k0 < K; k0 += BK) {
#pragma unroll
        for (int l = 0; l < A_LOADS; l++) {
            int idx = tid + l * THREADS;
            int r = idx / (BK / 4);
            int kc = (idx % (BK / 4)) * 4;
            As[kc + 0][r] = aReg[l].x;
            As[kc + 1][r] = aReg[l].y;
            As[kc + 2][r] = aReg[l].z;
            As[kc + 3][r] = aReg[l].w;
        }
#pragma unroll
        for (int l = 0; l < B_LOADS; l++) {
            int flat = (tid + l * THREADS) * 4;
            int k = flat / BN;
            int n = flat % BN;
            *(float4*)(&Bs[k][n]) = bReg[l];
        }
        __syncthreads();

        if (k0 + BK < K) {
#pragma unroll
            for (int l = 0; l < A_LOADS; l++) {
                int idx = tid + l * THREADS;
                int r = idx / (BK / 4);
                int kc = (idx % (BK / 4)) * 4;
                int row = m0 + r;
                if (row >= M) row = M - 1;
                aReg[l] = *(const float4*)(A + (size_t)row * K + k0 + BK + kc);
            }
#pragma unroll
            for (int l = 0; l < B_LOADS; l++) {
                int flat = (tid + l * THREADS) * 4;
                bReg[l] = *(const float4*)(B + (size_t)(k0 + BK) * N + flat);
            }
        }

#pragma unroll
        for (int kk = 0; kk < BK; kk += 8) {
            uint32_t ahi[MT][4], alo[MT][4];
#pragma unroll
            for (int mt = 0; mt < MT; mt++) {
                int r0 = wm0 + mt * 16 + p;
                f32_split(As[kk + q][r0],         ahi[mt][0], alo[mt][0]);
                f32_split(As[kk + q][r0 + 8],     ahi[mt][1], alo[mt][1]);
                f32_split(As[kk + q + 4][r0],     ahi[mt][2], alo[mt][2]);
                f32_split(As[kk + q + 4][r0 + 8], ahi[mt][3], alo[mt][3]);
            }
            uint32_t bhi[NT][2], blo[NT][2];
#pragma unroll
            for (int nt = 0; nt < NT; nt++) {
                int c0 = wn0 + nt * 8 + p;
                f32_split(Bs[kk + q][c0],     bhi[nt][0], blo[nt][0]);
                f32_split(Bs[kk + q + 4][c0], bhi[nt][1], blo[nt][1]);
            }
#pragma unroll
            for (int mt = 0; mt < MT; mt++)
#pragma unroll
                for (int nt = 0; nt < NT; nt++) {
                    mma_tf32(acc[mt][nt], ahi[mt], bhi[nt]);
                    mma_tf32(acc[mt][nt], ahi[mt], blo[nt]);
                    mma_tf32(acc[mt][nt], alo[mt], bhi[nt]);
                }
        }
        __syncthreads();
    }

#pragma unroll
    for (int mt = 0; mt < MT; mt++) {
        int row0 = m0 + wm0 + mt * 16 + p;
        int row1 = row0 + 8;
        float s0 = scale ? ((row0 < M) ? scale[row0] : 0.0f) : 1.0f;
        float s1 = scale ? ((row1 < M) ? scale[row1] : 0.0f) : 1.0f;
#pragma unroll
        for (int nt = 0; nt < NT; nt++) {
            int col = wn0 + nt * 8 + 2 * q;
            if (row0 < M) {
                if constexpr (sizeof(OutT) == 4) {
                    float2 v = make_float2(acc[mt][nt][0] * s0,
                                           acc[mt][nt][1] * s0);
                    *(float2*)((float*)C + (size_t)row0 * N + col) = v;
                } else {
                    __half2 v = __floats2half2_rn(acc[mt][nt][0] * s0,
                                                  acc[mt][nt][1] * s0);
                    *(__half2*)((__half*)C + (size_t)row0 * N + col) = v;
                }
            }
            if (row1 < M) {
                if constexpr (sizeof(OutT) == 4) {
                    float2 v = make_float2(acc[mt][nt][2] * s1,
                                           acc[mt][nt][3] * s1);
                    *(float2*)((float*)C + (size_t)row1 * N + col) = v;
                } else {
                    __half2 v = __floats2half2_rn(acc[mt][nt][2] * s1,
                                                  acc[mt][nt][3] * s1);
                    *(__half2*)((__half*)C + (size_t)row1 * N + col) = v;
                }
            }
        }
    }
}

// ---------------------------------------------------------------------------
// CSR pull aggregation (fp16 gathers via wide loads, fp32 accumulate)
// layer1: a1[n] = relu(dis[n] * (dis[n]*h1[n] + sum dis[s]*h1[s]) + b1)
// ---------------------------------------------------------------------------
__device__ __forceinline__ void acc_row16(float4& acc, const __half* rowp,
                                          int lane, float s) {
    uint2 u = ((const uint2*)rowp)[lane];  // one LDG.64 = 4 halves
    float2 lo = __half22float2(*(const __half2*)&u.x);
    float2 hi = __half22float2(*(const __half2*)&u.y);
    acc.x = fmaf(s, lo.x, acc.x);
    acc.y = fmaf(s, lo.y, acc.y);
    acc.z = fmaf(s, hi.x, acc.z);
    acc.w = fmaf(s, hi.y, acc.w);
}

__global__ __launch_bounds__(256) void k_agg1(const float* __restrict__ b1,
                                              int n) {
    int node = (blockIdx.x * blockDim.x + threadIdx.x) >> 5;
    int lane = threadIdx.x & 31;
    if (node >= n) return;
    int beg = g_off[node];
    int end = g_off[node + 1];
    float dn = g_dis[node];

    float4 acc = {0.f, 0.f, 0.f, 0.f};
    acc_row16(acc, g_h1 + (size_t)node * HID, lane, dn);  // self

    int j = beg;
    for (; j + 32 <= end; j += 32) {
        int s = g_src[j + lane];
        float ds = g_dis[s];
#pragma unroll 8
        for (int k = 0; k < 32; k++) {
            int sk = __shfl_sync(0xffffffff, s, k);
            float dsk = __shfl_sync(0xffffffff, ds, k);
            acc_row16(acc, g_h1 + (size_t)sk * HID, lane, dsk);
        }
    }
    if (j < end) {
        int myi = j + lane;
        int s = (myi < end) ? g_src[myi] : 0;
        float ds = (myi < end) ? g_dis[s] : 0.0f;
        int cnt = end - j;
        for (int k = 0; k < cnt; k++) {
            int sk = __shfl_sync(0xffffffff, s, k);
            float dsk = __shfl_sync(0xffffffff, ds, k);
            acc_row16(acc, g_h1 + (size_t)sk * HID, lane, dsk);
        }
    }

    float4 b = ((const float4*)b1)[lane];
    float4 o;
    o.x = fmaxf(fmaf(acc.x, dn, b.x), 0.0f);
    o.y = fmaxf(fmaf(acc.y, dn, b.y), 0.0f);
    o.z = fmaxf(fmaf(acc.z, dn, b.z), 0.0f);
    o.w = fmaxf(fmaf(acc.w, dn, b.w), 0.0f);
    ((float4*)(g_a1 + (size_t)node * HID))[lane] = o;
}

// layer2 (h2 rows pre-scaled by dis): out[n] = dis[n]*(h2[n]+sum h2[s]) + b2
__global__ __launch_bounds__(256) void k_agg2(const float* __restrict__ b2,
                                              float* __restrict__ out, int n) {
    int node = (blockIdx.x * blockDim.x + threadIdx.x) >> 5;
    int lane = threadIdx.x & 31;
    if (node >= n) return;
    int beg = g_off[node];
    int end = g_off[node + 1];

    float2 acc = __half22float2(
        ((const __half2*)(g_h2 + (size_t)node * OUTD))[lane]);  // self

    int j = beg;
    for (; j + 32 <= end; j += 32) {
        int s = g_src[j + lane];
#pragma unroll 8
        for (int k = 0; k < 32; k++) {
            int sk = __shfl_sync(0xffffffff, s, k);
            float2 v = __half22float2(
                ((const __half2*)(g_h2 + (size_t)sk * OUTD))[lane]);
            acc.x += v.x; acc.y += v.y;
        }
    }
    if (j < end) {
        int myi = j + lane;
        int s = (myi < end) ? g_src[myi] : 0;
        int cnt = end - j;
        for (int k = 0; k < cnt; k++) {
            int sk = __shfl_sync(0xffffffff, s, k);
            float2 v = __half22float2(
                ((const __half2*)(g_h2 + (size_t)sk * OUTD))[lane]);
            acc.x += v.x; acc.y += v.y;
        }
    }

    float sc = g_dis[node];
    float2 b = ((const float2*)b2)[lane];
    float2 o;
    o.x = fmaf(acc.x, sc, b.x);
    o.y = fmaf(acc.y, sc, b.y);
    ((float2*)(out + (size_t)node * OUTD))[lane] = o;
}

// ---------------------------------------------------------------------------
// launch (dual-stream: GEMM1 overlaps the whole CSR build)
// ---------------------------------------------------------------------------
extern "C" void kernel_launch(void* const* d_in, const int* in_sizes, int n_in,
                              void* d_out, int out_size) {
    const float* x = nullptr;
    const void* ei = nullptr;
    const float* W1 = nullptr;
    const float* b1 = nullptr;
    const float* W2 = nullptr;
    const float* b2 = nullptr;
    for (int i = 0; i < n_in; i++) {
        switch (in_sizes[i]) {
            case NN * IND:   x  = (const float*)d_in[i]; break;
            case 2 * NE:     ei = d_in[i];               break;
            case IND * HID:  W1 = (const float*)d_in[i]; break;
            case HID:        b1 = (const float*)d_in[i]; break;
            case HID * OUTD: W2 = (const float*)d_in[i]; break;
            case OUTD:       b2 = (const float*)d_in[i]; break;
            default: break;
        }
    }
    float* out = (float*)d_out;
    const int n = NN;
    const int e = NE;

    __half* h1; cudaGetSymbolAddress((void**)&h1, g_h1);
    float*  a1; cudaGetSymbolAddress((void**)&a1, g_a1);
    __half* h2; cudaGetSymbolAddress((void**)&h2, g_h2);
    float* dis; cudaGetSymbolAddress((void**)&dis, g_dis);
    int*  degi; cudaGetSymbolAddress((void**)&degi, g_degi);

    // capture-time fork; stream/event creation happens once per capture call
    cudaStream_t sB;
    cudaEvent_t e0, e1;
    cudaStreamCreateWithFlags(&sB, cudaStreamNonBlocking);
    cudaEventCreateWithFlags(&e0, cudaEventDisableTiming);
    cudaEventCreateWithFlags(&e1, cudaEventDisableTiming);

    // fork: GEMM1 on sB (depends only on inputs)
    cudaEventRecord(e0, 0);
    cudaStreamWaitEvent(sB, e0, 0);
    tf32_gemm<IND, HID, 128, 32, 64, 32, __half>
        <<<(n + 127) / 128, 256, 0, sB>>>(x, W1, h1, nullptr, n);
    cudaEventRecord(e1, sB);

    // default stream: CSR build
    cudaMemsetAsync(degi, 0, NN * sizeof(int));
    k_convert_deg<<<2048, 256>>>(ei, e);
    k_scan1<<<NB, 1024>>>(n);
    k_scan2<<<1, 32>>>();
    k_scan3<<<(n + 255) / 256, 256>>>(n);
    k_scatter<<<1024, 256>>>(e);

    // join, then aggregation + layer 2
    cudaStreamWaitEvent(0, e1, 0);
    {
        long long thr = (long long)n * 32;
        k_agg1<<<(int)((thr + 255) / 256), 256>>>(b1, n);
    }
    tf32_gemm<HID, OUTD, 128, 32, 32, 32, __half>
        <<<(n + 127) / 128, 256>>>(a1, W2, h2, dis, n);
    {
        long long thr = (long long)n * 32;
        k_agg2<<<(int)((thr + 255) / 256), 256>>>(b2, out, n);
    }
}